// round 17
// baseline (speedup 1.0000x reference)
#include <cuda_runtime.h>
#include <cuda_bf16.h>
#include <math.h>
#include <cstdint>

#define T_STEPS 32768
#define SZ 512
#define DIN 1024
#define HID 768

// scratch
__device__ float g_wp[(size_t)DIN * SZ];            // W' = Wl @ We
__device__ float g_wpt[(size_t)SZ * DIN];           // W'^T [N,K], pre-rounded tf32
__device__ float g_bw[SZ];                          // bW = b  @ We
__device__ float g_z[(size_t)T_STEPS * SZ];
__device__ float g_c0w[SZ];
__device__ __nv_bfloat16 g_zwb[(size_t)T_STEPS * SZ];   // zw logits, bf16
__device__ __nv_bfloat16 g_zbf[(size_t)T_STEPS * SZ];
__device__ __nv_bfloat16 g_wft[(size_t)SZ * SZ];    // Wf^T bf16 [N,K]

__device__ __forceinline__ uint32_t f2tf(float x) {
    uint32_t r; asm("cvt.rna.tf32.f32 %0, %1;" : "=r"(r) : "f"(x)); return r;
}
__device__ __forceinline__ void mma_tf32(float* c, const uint32_t* a, const uint32_t* b) {
    asm volatile(
        "mma.sync.aligned.m16n8k8.row.col.f32.tf32.tf32.f32 "
        "{%0,%1,%2,%3}, {%4,%5,%6,%7}, {%8,%9}, {%0,%1,%2,%3};"
        : "+f"(c[0]), "+f"(c[1]), "+f"(c[2]), "+f"(c[3])
        : "r"(a[0]), "r"(a[1]), "r"(a[2]), "r"(a[3]), "r"(b[0]), "r"(b[1]));
}
__device__ __forceinline__ void mma_bf16(float* c, const uint32_t* a, const uint32_t* b) {
    asm volatile(
        "mma.sync.aligned.m16n8k16.row.col.f32.bf16.bf16.f32 "
        "{%0,%1,%2,%3}, {%4,%5,%6,%7}, {%8,%9}, {%0,%1,%2,%3};"
        : "+f"(c[0]), "+f"(c[1]), "+f"(c[2]), "+f"(c[3])
        : "r"(a[0]), "r"(a[1]), "r"(a[2]), "r"(a[3]), "r"(b[0]), "r"(b[1]));
}
__device__ __forceinline__ void cpasync16(uint32_t dst, const void* src) {
    asm volatile("cp.async.ca.shared.global [%0], [%1], 16;" :: "r"(dst), "l"(src));
}
__device__ __forceinline__ void cp_commit() {
    asm volatile("cp.async.commit_group;" ::: "memory");
}
__device__ __forceinline__ void cp_wait0() {
    asm volatile("cp.async.wait_group 0;" ::: "memory");
}
__device__ __forceinline__ void cp_wait1() {
    asm volatile("cp.async.wait_group 1;" ::: "memory");
}

// ---------------------------------------------------------------------------
// tf32 z-GEMM v4: BM=128, BN=128, BK=32, 3-stage cp.async pipeline.
// 8 warps: warpM 0..3, warpN 0..1; warp tile 32x64.
// ---------------------------------------------------------------------------
#define ZSTR 36
#define ZA_ELEMS (128 * ZSTR)
#define ZB_ELEMS (128 * ZSTR)
#define Z_STAGE (ZA_ELEMS + ZB_ELEMS)
#define Z_SMEM (3 * Z_STAGE * 4)              // 110592 bytes

__global__ __launch_bounds__(256)
void ztf_kernel(const float* __restrict__ X0, const float* __restrict__ X1,
                const float* __restrict__ WpT, const float* __restrict__ bW,
                float* __restrict__ Z, __nv_bfloat16* __restrict__ Zbf)
{
    extern __shared__ __align__(16) uint32_t dsm[];   // [3][A | B]
    const uint32_t sbase = (uint32_t)__cvta_generic_to_shared(dsm);

    const int tid = threadIdx.x;
    const int wid = tid >> 5, lid = tid & 31;
    const int warpM = wid >> 1, warpN = wid & 1;
    const int bm = blockIdx.y * 128;
    const int bn = blockIdx.x * 128;
    const int lq = lid >> 2, lrm = lid & 3;
    const int arow = tid >> 3, agrp = tid & 7;

    float acc[2][8][4];
#pragma unroll
    for (int m = 0; m < 2; m++)
#pragma unroll
        for (int n = 0; n < 8; n++)
#pragma unroll
            for (int q = 0; q < 4; q++) acc[m][n][q] = 0.f;

    auto issueLoads = [&](int k0, int buf) {
        const uint32_t ab = sbase + (uint32_t)buf * Z_STAGE * 4;
        const uint32_t bb = ab + (uint32_t)ZA_ELEMS * 4;
        const int col = k0 + agrp * 4;
#pragma unroll
        for (int i = 0; i < 4; i++) {
            const int row = arow + i * 32;
            const float* src = (col < 512)
                ? (X0 + (size_t)(bm + row) * 512 + col)
                : (X1 + (size_t)(bm + row) * 512 + (col - 512));
            cpasync16(ab + (uint32_t)(row * ZSTR + agrp * 4) * 4, src);
        }
#pragma unroll
        for (int i = 0; i < 4; i++) {
            const int row = arow + i * 32;
            cpasync16(bb + (uint32_t)(row * ZSTR + agrp * 4) * 4,
                      WpT + (size_t)(bn + row) * DIN + k0 + agrp * 4);
        }
    };

    issueLoads(0, 0); cp_commit();
    issueLoads(32, 1); cp_commit();

    const int nit = DIN / 32;
    for (int it = 0; it < nit; it++) {
        if (it + 2 < nit) cp_wait1(); else cp_wait0();
        __syncthreads();

        const uint32_t* Ab = dsm + (it % 3) * Z_STAGE;
        const uint32_t* Bb = Ab + ZA_ELEMS;
#pragma unroll
        for (int ks = 0; ks < 4; ks++) {
            const int kb = ks * 8;
            uint32_t afr[2][4], bfr[8][2];
#pragma unroll
            for (int m = 0; m < 2; m++) {
                const uint32_t* ap = &Ab[(warpM * 32 + m * 16 + lq) * ZSTR + kb + lrm];
                afr[m][0] = ap[0];
                afr[m][1] = ap[8 * ZSTR];
                afr[m][2] = ap[4];
                afr[m][3] = ap[8 * ZSTR + 4];
            }
#pragma unroll
            for (int n = 0; n < 8; n++) {
                const uint32_t* bp = &Bb[(warpN * 64 + n * 8 + lq) * ZSTR + kb + lrm];
                bfr[n][0] = bp[0];
                bfr[n][1] = bp[4];
            }
#pragma unroll
            for (int m = 0; m < 2; m++)
#pragma unroll
                for (int n = 0; n < 8; n++)
                    mma_tf32(acc[m][n], afr[m], bfr[n]);
        }
        if (it + 2 < nit) {
            issueLoads((it + 2) * 32, (it + 2) % 3);
            cp_commit();
        }
    }

    // epilogue: sigmoid(acc + bW), fp32 + bf16 mirror
#pragma unroll
    for (int m = 0; m < 2; m++) {
#pragma unroll
        for (int n = 0; n < 8; n++) {
            const int gr0 = bm + warpM * 32 + m * 16 + lq;
            const int gc = bn + warpN * 64 + n * 8 + lrm * 2;
            const float b0 = bW[gc], b1 = bW[gc + 1];
#pragma unroll
            for (int h = 0; h < 2; h++) {
                const int gr = gr0 + h * 8;
                float vx = 1.f / (1.f + expf(-(acc[m][n][2 * h + 0] + b0)));
                float vy = 1.f / (1.f + expf(-(acc[m][n][2 * h + 1] + b1)));
                *reinterpret_cast<float2*>(Z + (size_t)gr * SZ + gc) = make_float2(vx, vy);
                *reinterpret_cast<__nv_bfloat162*>(Zbf + (size_t)gr * SZ + gc) =
                    __nv_bfloat162(__float2bfloat16(vx), __float2bfloat16(vy));
            }
        }
    }
}

// ---------------------------------------------------------------------------
// HMMA bf16 GEMM (BN=128, R16-proven), bf16 output (logits only).
// ---------------------------------------------------------------------------
#define ASTR 80

__global__ __launch_bounds__(256)
void hgemm_kernel(const __nv_bfloat16* __restrict__ A,
                  const __nv_bfloat16* __restrict__ Bt,
                  __nv_bfloat16* __restrict__ C)
{
    __shared__ __align__(16) char As[2][128 * ASTR];
    __shared__ __align__(16) char Bs[2][128 * ASTR];
    const int tid = threadIdx.x;
    const int wid = tid >> 5, lid = tid & 31;
    const int warpM = wid >> 1, warpN = wid & 1;
    const int bm = blockIdx.y * 128;
    const int bn = blockIdx.x * 128;
    const int lq = lid >> 2, lrm = lid & 3;

    float acc[2][8][4];
#pragma unroll
    for (int m = 0; m < 2; m++)
#pragma unroll
        for (int n = 0; n < 8; n++)
#pragma unroll
            for (int q = 0; q < 4; q++) acc[m][n][q] = 0.f;

    auto loadA = [&](int k0, uint4* av) {
#pragma unroll
        for (int i = 0; i < 2; i++) {
            int slot = tid + i * 256;
            int row = slot >> 2, grp = slot & 3;
            av[i] = *reinterpret_cast<const uint4*>(A + (size_t)(bm + row) * 512 + k0 + grp * 8);
        }
    };
    auto loadB = [&](int k0, uint4* bv) {
#pragma unroll
        for (int i = 0; i < 2; i++) {
            int slot = tid + i * 256;
            int row = slot >> 2, grp = slot & 3;
            bv[i] = *reinterpret_cast<const uint4*>(Bt + (size_t)(bn + row) * 512 + k0 + grp * 8);
        }
    };
    auto stTile = [&](int buf, const uint4* av, const uint4* bv) {
#pragma unroll
        for (int i = 0; i < 2; i++) {
            int slot = tid + i * 256;
            int row = slot >> 2, grp = slot & 3;
            *reinterpret_cast<uint4*>(&As[buf][row * ASTR + grp * 16]) = av[i];
            *reinterpret_cast<uint4*>(&Bs[buf][row * ASTR + grp * 16]) = bv[i];
        }
    };

    {
        uint4 av[2], bv[2];
        loadA(0, av); loadB(0, bv);
        stTile(0, av, bv);
    }
    __syncthreads();

    const int nit = 512 / 32;
    for (int it = 0; it < nit; it++) {
        const int cur = it & 1;
        uint4 av[2], bv[2];
        const bool more = (it + 1 < nit);
        if (more) { loadA((it + 1) * 32, av); loadB((it + 1) * 32, bv); }

#pragma unroll
        for (int ks = 0; ks < 2; ks++) {
            const int kb = ks * 32 + lrm * 4;
            uint32_t afr[2][4], bfr[8][2];
#pragma unroll
            for (int m = 0; m < 2; m++) {
                const char* ab = &As[cur][(warpM * 32 + m * 16 + lq) * ASTR];
                afr[m][0] = *reinterpret_cast<const uint32_t*>(ab + kb);
                afr[m][1] = *reinterpret_cast<const uint32_t*>(ab + 8 * ASTR + kb);
                afr[m][2] = *reinterpret_cast<const uint32_t*>(ab + kb + 16);
                afr[m][3] = *reinterpret_cast<const uint32_t*>(ab + 8 * ASTR + kb + 16);
            }
#pragma unroll
            for (int n = 0; n < 8; n++) {
                const char* bb = &Bs[cur][(warpN * 64 + n * 8 + lq) * ASTR];
                bfr[n][0] = *reinterpret_cast<const uint32_t*>(bb + kb);
                bfr[n][1] = *reinterpret_cast<const uint32_t*>(bb + kb + 16);
            }
#pragma unroll
            for (int m = 0; m < 2; m++)
#pragma unroll
                for (int n = 0; n < 8; n++)
                    mma_bf16(acc[m][n], afr[m], bfr[n]);
        }
        if (more) {
            stTile(cur ^ 1, av, bv);
            __syncthreads();
        }
    }

#pragma unroll
    for (int m = 0; m < 2; m++) {
#pragma unroll
        for (int n = 0; n < 8; n++) {
            const int gr0 = bm + warpM * 32 + m * 16 + lq;
            const int gc = bn + warpN * 64 + n * 8 + lrm * 2;
            *reinterpret_cast<__nv_bfloat162*>(C + (size_t)gr0 * 512 + gc) =
                __nv_bfloat162(__float2bfloat16(acc[m][n][0]), __float2bfloat16(acc[m][n][1]));
            *reinterpret_cast<__nv_bfloat162*>(C + (size_t)(gr0 + 8) * 512 + gc) =
                __nv_bfloat162(__float2bfloat16(acc[m][n][2]), __float2bfloat16(acc[m][n][3]));
        }
    }
}

// ---------------------------------------------------------------------------
// fp32 GEMM for prep only (W' = Wl@We)
// ---------------------------------------------------------------------------
__global__ __launch_bounds__(256)
void sgemm_kernel(const float* __restrict__ A0, const float* __restrict__ B,
                  float* __restrict__ C, int M, int N, int K)
{
    __shared__ __align__(16) float As[2][8][128];
    __shared__ __align__(16) float Bs[2][8][128];
    const int tid = threadIdx.x;
    const int bm = blockIdx.y * 128;
    const int bn = blockIdx.x * 128;
    const int lr = tid >> 1;
    const int lk = (tid & 1) << 2;
    const int bk = tid >> 5;
    const int bn4 = (tid & 31) << 2;
    const int tx = tid & 15;
    const int ty = tid >> 4;

    float acc[8][8];
#pragma unroll
    for (int i = 0; i < 8; i++)
#pragma unroll
        for (int j = 0; j < 8; j++) acc[i][j] = 0.f;

    auto loadA = [&](int k0) -> float4 {
        return *reinterpret_cast<const float4*>(A0 + (size_t)(bm + lr) * K + k0 + lk);
    };
    auto loadB = [&](int k0) -> float4 {
        return *reinterpret_cast<const float4*>(B + (size_t)(k0 + bk) * N + bn + bn4);
    };
    auto stTile = [&](int buf, float4 av, float4 bv) {
        As[buf][lk + 0][lr] = av.x; As[buf][lk + 1][lr] = av.y;
        As[buf][lk + 2][lr] = av.z; As[buf][lk + 3][lr] = av.w;
        *reinterpret_cast<float4*>(&Bs[buf][bk][bn4]) = bv;
    };

    const int nit = K >> 3;
    {
        float4 av = loadA(0), bv = loadB(0);
        stTile(0, av, bv);
    }
    __syncthreads();

    for (int i = 0; i < nit; i++) {
        const int cur = i & 1;
        float4 av, bv;
        const bool more = (i + 1 < nit);
        if (more) { av = loadA((i + 1) << 3); bv = loadB((i + 1) << 3); }
#pragma unroll
        for (int kk = 0; kk < 8; kk++) {
            float a[8], b[8];
            *reinterpret_cast<float4*>(&a[0]) = *reinterpret_cast<const float4*>(&As[cur][kk][ty << 2]);
            *reinterpret_cast<float4*>(&a[4]) = *reinterpret_cast<const float4*>(&As[cur][kk][64 + (ty << 2)]);
            *reinterpret_cast<float4*>(&b[0]) = *reinterpret_cast<const float4*>(&Bs[cur][kk][tx << 2]);
            *reinterpret_cast<float4*>(&b[4]) = *reinterpret_cast<const float4*>(&Bs[cur][kk][64 + (tx << 2)]);
#pragma unroll
            for (int ii = 0; ii < 8; ii++)
#pragma unroll
                for (int jj = 0; jj < 8; jj++) acc[ii][jj] = fmaf(a[ii], b[jj], acc[ii][jj]);
        }
        if (more) {
            stTile(cur ^ 1, av, bv);
            __syncthreads();
        }
    }

#pragma unroll
    for (int i = 0; i < 8; i++) {
        int row = bm + (ty << 2) + (i & 3) + ((i >= 4) ? 64 : 0);
#pragma unroll
        for (int jh = 0; jh < 2; jh++) {
            int col = bn + (tx << 2) + jh * 64;
            float4 v;
            v.x = acc[i][jh * 4 + 0]; v.y = acc[i][jh * 4 + 1];
            v.z = acc[i][jh * 4 + 2]; v.w = acc[i][jh * 4 + 3];
            *reinterpret_cast<float4*>(C + (size_t)row * N + col) = v;
        }
    }
}

// ---------------------------------------------------------------------------
// transposes + prep
// ---------------------------------------------------------------------------
__global__ void wtrans_kernel(const float* __restrict__ Wf, __nv_bfloat16* __restrict__ WfT)
{
    __shared__ float tile[32][33];
    const int bx = blockIdx.x * 32, by = blockIdx.y * 32;
    const int tx = threadIdx.x, ty = threadIdx.y;
    for (int i = ty; i < 32; i += 8)
        tile[i][tx] = Wf[(size_t)(by + i) * SZ + bx + tx];
    __syncthreads();
    for (int i = ty; i < 32; i += 8)
        WfT[(size_t)(bx + i) * SZ + by + tx] = __float2bfloat16(tile[tx][i]);
}

__global__ void wtransf_kernel(const float* __restrict__ Wp, float* __restrict__ WpT)
{
    __shared__ float tile[32][33];
    const int bx = blockIdx.x * 32, by = blockIdx.y * 32;
    const int tx = threadIdx.x, ty = threadIdx.y;
    for (int i = ty; i < 32; i += 8)
        tile[i][tx] = Wp[(size_t)(by + i) * SZ + bx + tx];
    __syncthreads();
    for (int i = ty; i < 32; i += 8)
        WpT[(size_t)(bx + i) * DIN + by + tx] = __uint_as_float(f2tf(tile[tx][i]));
}

__global__ __launch_bounds__(512)
void bprep_kernel(const float* __restrict__ b, const float* __restrict__ We,
                  float* __restrict__ bW)
{
    const int j = threadIdx.x;
    float acc = 0.f;
    for (int k = 0; k < HID; k++)
        acc = fmaf(__ldg(b + k), __ldg(We + (size_t)k * SZ + j), acc);
    bW[j] = acc;
}

__global__ __launch_bounds__(512)
void cinit_kernel(const float* __restrict__ c0, const float* __restrict__ Wf,
                  float* __restrict__ c0w)
{
    __shared__ float c0s[512];
    const int tid = threadIdx.x;
    c0s[tid] = c0[tid];
    __syncthreads();
    float acc = 0.f;
    for (int i = 0; i < 512; i++)
        acc = fmaf(c0s[i], __ldg(Wf + (size_t)i * 512 + tid), acc);
    c0w[tid] = acc;
}

// ---------------------------------------------------------------------------
// Final fused sweep with inline rate computation:
// r_t = tanh(z[t]·Wr); out[t] = softmax(r_{t-1}·zw[t-1])⊙(r_{t-1}·z[t-1]) + r_t·z[t]
// t=0: logits = c0w (fp32), prev-state = c0, pscale = 1.
// ---------------------------------------------------------------------------
__global__ __launch_bounds__(256)
void sweep_final(const __nv_bfloat16* __restrict__ zwb, const float* __restrict__ z,
                 const float* __restrict__ Wr, const float* __restrict__ c0,
                 const float* __restrict__ c0w, float* __restrict__ out)
{
    __shared__ __align__(16) float ws[512];
    const int tid = threadIdx.x;
    ws[tid] = Wr[tid];
    ws[tid + 256] = Wr[tid + 256];
    __syncthreads();

    const int w = tid >> 5, l = tid & 31;
    const size_t row = (size_t)blockIdx.x * 8 + w;

    const float4* zr = reinterpret_cast<const float4*>(z + row * 512);
    const float4* Pr = (row == 0)
        ? reinterpret_cast<const float4*>(c0)
        : reinterpret_cast<const float4*>(z + (row - 1) * 512);
    const float4* wsp = reinterpret_cast<const float4*>(ws);

    float4 zv[4], pv[4];
    float dt = 0.f, dp = 0.f;
#pragma unroll
    for (int q = 0; q < 4; q++) {
        zv[q] = zr[l + q * 32];
        pv[q] = Pr[l + q * 32];
        float4 wv = wsp[l + q * 32];
        dt += zv[q].x * wv.x + zv[q].y * wv.y + zv[q].z * wv.z + zv[q].w * wv.w;
        dp += pv[q].x * wv.x + pv[q].y * wv.y + pv[q].z * wv.z + pv[q].w * wv.w;
    }
#pragma unroll
    for (int m = 16; m >= 1; m >>= 1) {
        dt += __shfl_xor_sync(0xffffffffu, dt, m);
        dp += __shfl_xor_sync(0xffffffffu, dp, m);
    }
    const float rt = tanhf(dt);
    const float rp = tanhf(dp);
    const float scale = (row == 0) ? 1.f : rp;
    const float pscale = scale;

    // logits: bf16 zw[row-1] (or fp32 c0w for row 0)
    float4 lv[4];
    if (row == 0) {
        const float4* c4 = reinterpret_cast<const float4*>(c0w);
#pragma unroll
        for (int q = 0; q < 4; q++) lv[q] = c4[l + q * 32];
    } else {
        const uint2* lb = reinterpret_cast<const uint2*>(zwb + (row - 1) * 512);
#pragma unroll
        for (int q = 0; q < 4; q++) {
            uint2 raw = lb[l + q * 32];
            float2 f0 = __bfloat1622float2(*reinterpret_cast<__nv_bfloat162*>(&raw.x));
            float2 f1 = __bfloat1622float2(*reinterpret_cast<__nv_bfloat162*>(&raw.y));
            lv[q] = make_float4(f0.x, f0.y, f1.x, f1.y);
        }
    }

    float4 e[4];
    float s = 0.f;
#pragma unroll
    for (int q = 0; q < 4; q++) {
        e[q].x = __expf(scale * lv[q].x);
        e[q].y = __expf(scale * lv[q].y);
        e[q].z = __expf(scale * lv[q].z);
        e[q].w = __expf(scale * lv[q].w);
        s += (e[q].x + e[q].y) + (e[q].z + e[q].w);
    }
#pragma unroll
    for (int m = 16; m >= 1; m >>= 1) s += __shfl_xor_sync(0xffffffffu, s, m);
    const float g = pscale / s;

    float4* dst = reinterpret_cast<float4*>(out + row * 512);
#pragma unroll
    for (int q = 0; q < 4; q++) {
        float4 o;
        o.x = fmaf(e[q].x * g, pv[q].x, rt * zv[q].x);
        o.y = fmaf(e[q].y * g, pv[q].y, rt * zv[q].y);
        o.z = fmaf(e[q].z * g, pv[q].z, rt * zv[q].z);
        o.w = fmaf(e[q].w * g, pv[q].w, rt * zv[q].w);
        dst[l + q * 32] = o;
    }
}

// ---------------------------------------------------------------------------
extern "C" void kernel_launch(void* const* d_in, const int* in_sizes, int n_in,
                              void* d_out, int out_size)
{
    const float* x1 = (const float*)d_in[0];
    const float* x2 = (const float*)d_in[1];
    const float* c0 = (const float*)d_in[2];
    const float* Wl = (const float*)d_in[3];
    const float* bl = (const float*)d_in[4];
    const float* We = (const float*)d_in[5];
    const float* Wr = (const float*)d_in[6];
    const float* Wf = (const float*)d_in[7];
    float* out = (float*)d_out;

    float *Wp, *WpT, *bW, *zz, *c0w;
    __nv_bfloat16 *zwb, *zbf, *wft;
    cudaGetSymbolAddress((void**)&Wp, g_wp);
    cudaGetSymbolAddress((void**)&WpT, g_wpt);
    cudaGetSymbolAddress((void**)&bW, g_bw);
    cudaGetSymbolAddress((void**)&zz, g_z);
    cudaGetSymbolAddress((void**)&c0w, g_c0w);
    cudaGetSymbolAddress((void**)&zwb, g_zwb);
    cudaGetSymbolAddress((void**)&zbf, g_zbf);
    cudaGetSymbolAddress((void**)&wft, g_wft);

    static bool attr_done = false;
    if (!attr_done) {
        cudaFuncSetAttribute(ztf_kernel, cudaFuncAttributeMaxDynamicSharedMemorySize, Z_SMEM);
        attr_done = true;
    }

    dim3 gW(SZ / 128, DIN / 128);
    dim3 gT(SZ / 128, T_STEPS / 128);
    const int rowsg = T_STEPS / 8;

    // prep
    sgemm_kernel<<<gW, 256>>>(Wl, We, Wp, DIN, SZ, HID);
    bprep_kernel<<<1, 512>>>(bl, We, bW);
    wtrans_kernel<<<dim3(16, 16), dim3(32, 8)>>>(Wf, wft);
    wtransf_kernel<<<dim3(SZ / 32, DIN / 32), dim3(32, 8)>>>(Wp, WpT);
    cinit_kernel<<<1, 512>>>(c0, Wf, c0w);

    // z = sigmoid(X @ W' + bW)  (tf32, 3-stage cp.async)
    ztf_kernel<<<gT, 256, Z_SMEM>>>(x1, x2, WpT, bW, zz, zbf);

    // zw = z @ Wf  (HMMA bf16, bf16 out)
    hgemm_kernel<<<gT, 256>>>(zbf, wft, zwb);

    // fused Picard sweep (rate inline) -> out
    sweep_final<<<rowsg, 256>>>(zwb, zz, Wr, c0, c0w, out);
}